// round 6
// baseline (speedup 1.0000x reference)
#include <cuda_runtime.h>
#include <cuda_fp16.h>
#include <cstdint>

// N=25000 nodes, E=400000 edges, D=32.
// out[i,h] = sum_{e: dst_e=i} msgs[e,h] + sum_d x[i,d]*node_W[h,d]
// msgs[e,h] = sum_k edge_attr[e,k] * Y[src_e, k*32+h]
// Y[j, c]   = sum_d x[j,d] * W2[d,c],  W2[d, k*32+h] = edge_W[(d*32+h)*32 + k]

#define DD 32
#define N_MAX 25000
#define E_MAX 400000
#define KH 1024   // D*D

__device__ __half g_Y[(size_t)N_MAX * KH];    // 51.2 MB (fp16)
__device__ float g_Bfh[32768];                // tf32-hi B fragments
__device__ float g_Bfl[32768];                // tf32-lo B fragments
__device__ int   g_hist[N_MAX];               // zero at entry; re-zeroed in scan
__device__ int   g_cursor[N_MAX];
__device__ int   g_perm[E_MAX + 32];
__device__ int   g_ssorted[E_MAX + 32];
__device__ int   g_dsorted[E_MAX + 32];
__device__ unsigned g_ctr;                    // last-block-done counter (0 init)

__device__ __forceinline__ void red_add_v4(float* addr, float4 v) {
    asm volatile("red.global.add.v4.f32 [%0], {%1,%2,%3,%4};"
                 :: "l"(addr), "f"(v.x), "f"(v.y), "f"(v.z), "f"(v.w)
                 : "memory");
}

__device__ __forceinline__ void mma_tf32(float* c, const unsigned* a,
                                         unsigned b0, unsigned b1) {
    asm volatile(
        "mma.sync.aligned.m16n8k8.row.col.f32.tf32.tf32.f32 "
        "{%0,%1,%2,%3}, {%4,%5,%6,%7}, {%8,%9}, {%0,%1,%2,%3};"
        : "+f"(c[0]), "+f"(c[1]), "+f"(c[2]), "+f"(c[3])
        : "r"(a[0]), "r"(a[1]), "r"(a[2]), "r"(a[3]), "r"(b0), "r"(b1));
}

__device__ __forceinline__ void split_tf32(float v, unsigned& hi, unsigned& lo) {
    unsigned u = __float_as_uint(v) & 0xFFFFE000u;
    hi = u;
    lo = __float_as_uint(v - __uint_as_float(u));
}

// ---------------------------------------------------------------------------
// Launch 1: [0,BF_B): tf32 B-fragments + pad fill | [BF_B,..): src histogram.
// Last block to finish runs the exclusive scan (hist -> cursor) and re-zeroes
// hist + counter for graph replay.
// ---------------------------------------------------------------------------
__global__ void setup_kernel(const float* __restrict__ edge_W,
                             const int*   __restrict__ edge_index,
                             int N, int E, int BF_B) {
    __shared__ int wsum[32];
    __shared__ bool isLast;

    if (blockIdx.x < BF_B) {
        int idx = blockIdx.x * 256 + threadIdx.x;
        if (idx < 32768) {
            int reg  = idx & 1;
            int lane = (idx >> 1) & 31;
            int ks   = (idx >> 6) & 3;
            int nt   = idx >> 8;
            int d = ks * 8 + reg * 4 + (lane & 3);
            int c = nt * 8 + (lane >> 2);
            float w = edge_W[(d * 32 + (c & 31)) * 32 + (c >> 5)];
            unsigned hi, lo;
            split_tf32(w, hi, lo);
            g_Bfh[idx] = __uint_as_float(hi);
            g_Bfl[idx] = __uint_as_float(lo);
        }
        if (blockIdx.x == 0 && threadIdx.x < 32) {
            int e = E + threadIdx.x;   // pad region for the edge kernel
            g_perm[e] = 0; g_ssorted[e] = 0; g_dsorted[e] = 0;
        }
    } else {
        int base = ((blockIdx.x - BF_B) * 256 + threadIdx.x) * 4;
        #pragma unroll
        for (int j = 0; j < 4; j++) {
            int e = base + j;
            if (e < E) atomicAdd(&g_hist[edge_index[e]], 1);
        }
    }

    // ---- last-block-done: run the scan ----
    __threadfence();
    __syncthreads();
    if (threadIdx.x == 0)
        isLast = (atomicAdd(&g_ctr, 1u) == gridDim.x - 1);
    __syncthreads();
    if (!isLast) return;

    int t = threadIdx.x;                 // 256 threads
    int C = (N + 255) / 256;
    int base = t * C;
    int total = 0;
    for (int j = 0; j < C; j++) {
        int i = base + j;
        if (i < N) total += __ldcg(&g_hist[i]);
    }
    int lane = t & 31, wid = t >> 5;
    int incl = total;
    #pragma unroll
    for (int off = 1; off < 32; off <<= 1) {
        int n = __shfl_up_sync(0xffffffffu, incl, off);
        if (lane >= off) incl += n;
    }
    if (lane == 31) wsum[wid] = incl;
    __syncthreads();
    if (wid == 0 && lane < 8) {
        int s = wsum[lane];
        #pragma unroll
        for (int off = 1; off < 8; off <<= 1) {
            int n = __shfl_up_sync(0x000000ffu, s, off);
            if (lane >= off) s += n;
        }
        wsum[lane] = s;
    }
    __syncthreads();
    int run = ((wid == 0) ? 0 : wsum[wid - 1]) + incl - total;
    for (int j = 0; j < C; j++) {
        int i = base + j;
        if (i < N) {
            g_cursor[i] = run;
            run += __ldcg(&g_hist[i]);
            g_hist[i] = 0;            // ready for next replay
        }
    }
    if (t == 0) g_ctr = 0;            // reset counter for next replay
}

// ---------------------------------------------------------------------------
// Launch 2: mega-kernel. [0,SCAT_B) scatter | [..,+GEMM_B) tf32 Y-gemm | node.
// ---------------------------------------------------------------------------
__global__ void mega_kernel(const int*   __restrict__ edge_index,
                            const float* __restrict__ x,
                            const float* __restrict__ node_W,
                            float* __restrict__ out,
                            int N, int E, int SCAT_B, int GEMM_B) {
    __shared__ union {
        float4 sBf[8][4][32];                                    // 16 KB
        struct { float sWT[DD * DD]; float sx[8][DD]; } n;
    } sm;
    int bx = blockIdx.x;
    int tx = threadIdx.x;

    if (bx < SCAT_B) {
        // ---- scatter edges into src-sorted order (2 per thread) ----
        int e0 = bx * 512 + tx;
        int e1 = e0 + 256;
        int s0 = -1, s1 = -1, d0 = 0, d1 = 0;
        if (e0 < E) { s0 = edge_index[e0]; d0 = edge_index[E + e0]; }
        if (e1 < E) { s1 = edge_index[e1]; d1 = edge_index[E + e1]; }
        int p0 = (s0 >= 0) ? atomicAdd(&g_cursor[s0], 1) : 0;
        int p1 = (s1 >= 0) ? atomicAdd(&g_cursor[s1], 1) : 0;
        if (s0 >= 0) { g_perm[p0] = e0; g_ssorted[p0] = s0; g_dsorted[p0] = d0; }
        if (s1 >= 0) { g_perm[p1] = e1; g_ssorted[p1] = s1; g_dsorted[p1] = d1; }
    } else if (bx < SCAT_B + GEMM_B) {
        // ---- Y = x @ W2 via tf32 MMA, 3-pass hi/lo; fp16 store ----
        int gb = bx - SCAT_B;
        int mb = gb >> 4;
        int cb = gb & 15;
        int c0 = cb * 64;

        for (int i = tx; i < 1024; i += 256) {
            float2 h = ((const float2*)g_Bfh)[cb * 1024 + i];
            float2 l = ((const float2*)g_Bfl)[cb * 1024 + i];
            int lane_ = i & 31, ks_ = (i >> 5) & 3, nt_ = i >> 7;
            sm.sBf[nt_][ks_][lane_] = make_float4(h.x, h.y, l.x, l.y);
        }
        __syncthreads();

        int w = tx >> 5, lane = tx & 31;
        int gid = lane >> 2, tig = lane & 3;
        int Nc = N - 1;

        for (int mp = 0; mp < 4; mp++) {
            int rbase = mb * 1024 + w * 128 + mp * 32;
            float C[2][8][4];
            #pragma unroll
            for (int m2 = 0; m2 < 2; m2++)
                #pragma unroll
                for (int nt = 0; nt < 8; nt++)
                    #pragma unroll
                    for (int r = 0; r < 4; r++) C[m2][nt][r] = 0.f;

            #pragma unroll
            for (int ks = 0; ks < 4; ks++) {
                unsigned ah[2][4], al[2][4];
                #pragma unroll
                for (int m2 = 0; m2 < 2; m2++) {
                    int rA  = rbase + m2 * 16;
                    int ra0 = min(rA + gid, Nc);
                    int ra1 = min(rA + gid + 8, Nc);
                    float v0 = x[ra0 * 32 + ks * 8 + tig];
                    float v1 = x[ra1 * 32 + ks * 8 + tig];
                    float v2 = x[ra0 * 32 + ks * 8 + tig + 4];
                    float v3 = x[ra1 * 32 + ks * 8 + tig + 4];
                    split_tf32(v0, ah[m2][0], al[m2][0]);
                    split_tf32(v1, ah[m2][1], al[m2][1]);
                    split_tf32(v2, ah[m2][2], al[m2][2]);
                    split_tf32(v3, ah[m2][3], al[m2][3]);
                }
                #pragma unroll
                for (int nt = 0; nt < 8; nt++) {
                    float4 b = sm.sBf[nt][ks][lane];
                    unsigned bh0 = __float_as_uint(b.x), bh1 = __float_as_uint(b.y);
                    unsigned bl0 = __float_as_uint(b.z), bl1 = __float_as_uint(b.w);
                    #pragma unroll
                    for (int m2 = 0; m2 < 2; m2++) {
                        mma_tf32(C[m2][nt], ah[m2], bh0, bh1);
                        mma_tf32(C[m2][nt], al[m2], bh0, bh1);
                        mma_tf32(C[m2][nt], ah[m2], bl0, bl1);
                    }
                }
            }
            #pragma unroll
            for (int m2 = 0; m2 < 2; m2++) {
                int rA  = rbase + m2 * 16;
                int r0s = rA + gid, r1s = r0s + 8;
                #pragma unroll
                for (int nt = 0; nt < 8; nt++) {
                    int c = c0 + nt * 8 + 2 * tig;
                    if (r0s < N)
                        *(__half2*)&g_Y[(size_t)r0s * KH + c] =
                            __floats2half2_rn(C[m2][nt][0], C[m2][nt][1]);
                    if (r1s < N)
                        *(__half2*)&g_Y[(size_t)r1s * KH + c] =
                            __floats2half2_rn(C[m2][nt][2], C[m2][nt][3]);
                }
            }
        }
    } else {
        // ---- out[i,h] = sum_d x[i,d] * node_W[h,d]  (32 nodes/block) ----
        int nb = bx - SCAT_B - GEMM_B;
        for (int i = tx; i < DD * DD; i += 256) {
            int h = i & 31, d = i >> 5;
            sm.n.sWT[d * 32 + h] = node_W[h * 32 + d];
        }
        __syncthreads();
        int r = tx >> 5, h = tx & 31;
        for (int it = 0; it < 4; it++) {
            int node = nb * 32 + it * 8 + r;
            if (node < N) sm.n.sx[r][h] = x[node * DD + h];
            __syncthreads();
            if (node < N) {
                float acc = 0.f;
                #pragma unroll
                for (int d = 0; d < DD; d++)
                    acc += sm.n.sx[r][d] * sm.n.sWT[d * 32 + h];
                out[node * DD + h] = acc;
            }
            __syncthreads();
        }
    }
}

// ---------------------------------------------------------------------------
// Launch 3: edge messages. Warp = 32 consecutive src-sorted edges (4 warps/blk).
// edge_attr staged in SMEM (pitch 36 -> broadcast LDS.128). Same-src runs via
// ballot; fp16 Y row converted once per run into 32 fp32 regs.
// ---------------------------------------------------------------------------
__global__ void edge_kernel32(const float* __restrict__ edge_attr,
                              float* __restrict__ out, int E) {
    __shared__ float eas[4][32 * 36];   // 18 KB
    int w    = threadIdx.x >> 5;
    int lane = threadIdx.x & 31;
    int gw = blockIdx.x * 4 + w;
    int e0 = gw * 32;
    if (e0 >= E) return;                 // warp-uniform

    int p32 = g_perm[e0 + lane];         // padded region valid for e>=E
    int s32 = g_ssorted[e0 + lane];
    int d32 = g_dsorted[e0 + lane];

    // stage edge_attr rows (zero for padded edges)
    float* easw = &eas[w][0];
    #pragma unroll
    for (int i = 0; i < 32; i++) {
        int pi = __shfl_sync(0xffffffffu, p32, i);
        float v = 0.f;
        if (e0 + i < E) v = edge_attr[(size_t)pi * DD + lane];
        easw[i * 36 + lane] = v;
    }
    __syncwarp();

    // same-src run starts among the 32 edges
    int prevs = __shfl_up_sync(0xffffffffu, s32, 1);
    bool isStart = (lane == 0) || (s32 != prevs);
    unsigned startm = __ballot_sync(0xffffffffu, isStart);

    int g8 = lane & 24;      // k-group base
    int h4 = lane & 7;       // h-quad index
    while (startm) {
        int i = __ffs(startm) - 1;
        startm &= startm - 1;
        int nxt = startm ? (__ffs(startm) - 1) : 32;
        int s = __shfl_sync(0xffffffffu, s32, i);
        const __half* Yrow = g_Y + (size_t)s * KH;
        float4 y[8];
        #pragma unroll
        for (int j = 0; j < 8; j++) {
            uint2 v = *(const uint2*)(Yrow + (g8 + j) * 32 + h4 * 4);
            float2 f01 = __half22float2(*(__half2*)&v.x);
            float2 f23 = __half22float2(*(__half2*)&v.y);
            y[j] = make_float4(f01.x, f01.y, f23.x, f23.y);
        }

        for (int e = i; e < nxt; e++) {
            const float4* ep = (const float4*)(easw + e * 36 + g8);
            float4 f0 = ep[0];
            float4 f1 = ep[1];
            float4 acc;
            acc.x = f0.x * y[0].x; acc.y = f0.x * y[0].y;
            acc.z = f0.x * y[0].z; acc.w = f0.x * y[0].w;
            acc.x += f0.y * y[1].x; acc.y += f0.y * y[1].y;
            acc.z += f0.y * y[1].z; acc.w += f0.y * y[1].w;
            acc.x += f0.z * y[2].x; acc.y += f0.z * y[2].y;
            acc.z += f0.z * y[2].z; acc.w += f0.z * y[2].w;
            acc.x += f0.w * y[3].x; acc.y += f0.w * y[3].y;
            acc.z += f0.w * y[3].z; acc.w += f0.w * y[3].w;
            acc.x += f1.x * y[4].x; acc.y += f1.x * y[4].y;
            acc.z += f1.x * y[4].z; acc.w += f1.x * y[4].w;
            acc.x += f1.y * y[5].x; acc.y += f1.y * y[5].y;
            acc.z += f1.y * y[5].z; acc.w += f1.y * y[5].w;
            acc.x += f1.z * y[6].x; acc.y += f1.z * y[6].y;
            acc.z += f1.z * y[6].z; acc.w += f1.z * y[6].w;
            acc.x += f1.w * y[7].x; acc.y += f1.w * y[7].y;
            acc.z += f1.w * y[7].z; acc.w += f1.w * y[7].w;
            // combine k-group partners (0<->8, 16<->24)
            acc.x += __shfl_xor_sync(0xffffffffu, acc.x, 8);
            acc.y += __shfl_xor_sync(0xffffffffu, acc.y, 8);
            acc.z += __shfl_xor_sync(0xffffffffu, acc.z, 8);
            acc.w += __shfl_xor_sync(0xffffffffu, acc.w, 8);
            int dst = __shfl_sync(0xffffffffu, d32, e);
            if (!(lane & 8))
                red_add_v4(&out[(size_t)dst * DD + h4 * 4], acc);
        }
    }
}

// ---------------------------------------------------------------------------
// Launch.  inputs: 0:x[N*32] 1:edge_attr[E*32] 2:edge_W[1024*32] 3:node_W[32*32]
//          4:edge_index[2*E] i32.  out: [N*32] f32
// ---------------------------------------------------------------------------
extern "C" void kernel_launch(void* const* d_in, const int* in_sizes, int n_in,
                              void* d_out, int out_size) {
    const float* x         = (const float*)d_in[0];
    const float* edge_attr = (const float*)d_in[1];
    const float* edge_W    = (const float*)d_in[2];
    const float* node_W    = (const float*)d_in[3];
    const int*   edge_idx  = (const int*)  d_in[4];
    float* out = (float*)d_out;

    int N = in_sizes[0] / DD;
    int E = in_sizes[4] / 2;
    if (N > N_MAX) N = N_MAX;
    if (E > E_MAX) E = E_MAX;

    // 1. B-fragments + pad + histogram + (last block) scan
    int BF_B   = 32768 / 256;                   // 128
    int HIST_B = ((E + 3) / 4 + 255) / 256;
    setup_kernel<<<BF_B + HIST_B, 256>>>(edge_W, edge_idx, N, E, BF_B);

    // 2. scatter | tf32 Y-gemm | node_init
    int SCAT_B = (E + 511) / 512;
    int MB     = (N + 1023) / 1024;
    int GEMM_B = MB * 16;
    int NODE_B = (N + 31) / 32;
    mega_kernel<<<SCAT_B + GEMM_B + NODE_B, 256>>>(edge_idx, x, node_W, out,
                                                   N, E, SCAT_B, GEMM_B);

    // 3. edge messages + vector-red scatter
    int nwarps = (E + 31) / 32;
    edge_kernel32<<<(nwarps + 3) / 4, 128>>>(edge_attr, out, E);
}

// round 7
// speedup vs baseline: 1.3213x; 1.3213x over previous
#include <cuda_runtime.h>
#include <cuda_fp16.h>
#include <cstdint>

// N=25000 nodes, E=400000 edges, D=32.
// out[i,h] = sum_{e: dst_e=i} msgs[e,h] + sum_d x[i,d]*node_W[h,d]
// msgs[e,h] = sum_k edge_attr[e,k] * Y[src_e, k*32+h]
// Y[j, c]   = sum_d x[j,d] * W2[d,c],  W2[d, k*32+h] = edge_W[(d*32+h)*32 + k]

#define DD 32
#define N_MAX 25000
#define E_MAX 400000
#define KH 1024   // D*D

__device__ __half g_Y[(size_t)N_MAX * KH];    // 51.2 MB (fp16)
__device__ float g_Bfh[32768];                // tf32-hi B fragments
__device__ float g_Bfl[32768];                // tf32-lo B fragments
__device__ int   g_hist[N_MAX];               // zero at entry; re-zeroed by scan
__device__ int   g_cursor[N_MAX];
__device__ int   g_perm[E_MAX + 32];
__device__ int   g_ssorted[E_MAX + 32];
__device__ int   g_dsorted[E_MAX + 32];

__device__ __forceinline__ void red_add_v4(float* addr, float4 v) {
    asm volatile("red.global.add.v4.f32 [%0], {%1,%2,%3,%4};"
                 :: "l"(addr), "f"(v.x), "f"(v.y), "f"(v.z), "f"(v.w)
                 : "memory");
}

__device__ __forceinline__ void mma_tf32(float* c, const unsigned* a,
                                         unsigned b0, unsigned b1) {
    asm volatile(
        "mma.sync.aligned.m16n8k8.row.col.f32.tf32.tf32.f32 "
        "{%0,%1,%2,%3}, {%4,%5,%6,%7}, {%8,%9}, {%0,%1,%2,%3};"
        : "+f"(c[0]), "+f"(c[1]), "+f"(c[2]), "+f"(c[3])
        : "r"(a[0]), "r"(a[1]), "r"(a[2]), "r"(a[3]), "r"(b0), "r"(b1));
}

__device__ __forceinline__ void split_tf32(float v, unsigned& hi, unsigned& lo) {
    unsigned u = __float_as_uint(v) & 0xFFFFE000u;
    hi = u;
    lo = __float_as_uint(v - __uint_as_float(u));
}

// ---------------------------------------------------------------------------
// Launch 1: [0,BF_B): tf32 B-fragments + pad fill | [BF_B,..): src histogram.
// ---------------------------------------------------------------------------
__global__ void setup_kernel(const float* __restrict__ edge_W,
                             const int*   __restrict__ edge_index,
                             int E, int BF_B) {
    if (blockIdx.x < BF_B) {
        int idx = blockIdx.x * 256 + threadIdx.x;
        if (idx < 32768) {
            int reg  = idx & 1;
            int lane = (idx >> 1) & 31;
            int ks   = (idx >> 6) & 3;
            int nt   = idx >> 8;
            int d = ks * 8 + reg * 4 + (lane & 3);
            int c = nt * 8 + (lane >> 2);
            float w = edge_W[(d * 32 + (c & 31)) * 32 + (c >> 5)];
            unsigned hi, lo;
            split_tf32(w, hi, lo);
            g_Bfh[idx] = __uint_as_float(hi);
            g_Bfl[idx] = __uint_as_float(lo);
        }
        if (blockIdx.x == 0 && threadIdx.x < 32) {
            int e = E + threadIdx.x;   // pad region for the edge kernel
            g_perm[e] = 0; g_ssorted[e] = 0; g_dsorted[e] = 0;
        }
    } else {
        int base = ((blockIdx.x - BF_B) * 256 + threadIdx.x) * 4;
        #pragma unroll
        for (int j = 0; j < 4; j++) {
            int e = base + j;
            if (e < E) atomicAdd(&g_hist[edge_index[e]], 1);
        }
    }
}

// ---------------------------------------------------------------------------
// Launch 2: single-block exclusive scan -> g_cursor; re-zeroes g_hist.
// 1024 threads: 25-element serial chunks, warp+block scan of totals.
// ---------------------------------------------------------------------------
__global__ void scan_kernel(int N) {
    __shared__ int wsum[32];
    int t = threadIdx.x;                 // 1024 threads
    int C = (N + 1023) / 1024;
    int base = t * C;

    int total = 0;
    for (int j = 0; j < C; j++) {
        int i = base + j;
        if (i < N) total += g_hist[i];
    }
    int lane = t & 31, wid = t >> 5;
    int incl = total;
    #pragma unroll
    for (int off = 1; off < 32; off <<= 1) {
        int n = __shfl_up_sync(0xffffffffu, incl, off);
        if (lane >= off) incl += n;
    }
    if (lane == 31) wsum[wid] = incl;
    __syncthreads();
    if (wid == 0) {
        int s = wsum[lane];
        #pragma unroll
        for (int off = 1; off < 32; off <<= 1) {
            int n = __shfl_up_sync(0xffffffffu, s, off);
            if (lane >= off) s += n;
        }
        wsum[lane] = s;
    }
    __syncthreads();
    int run = ((wid == 0) ? 0 : wsum[wid - 1]) + incl - total;
    for (int j = 0; j < C; j++) {
        int i = base + j;
        if (i < N) {
            g_cursor[i] = run;
            run += g_hist[i];
            g_hist[i] = 0;            // ready for next graph replay
        }
    }
}

// ---------------------------------------------------------------------------
// Launch 3: mega-kernel. [0,SCAT_B) scatter | [..,+GEMM_B) tf32 Y-gemm | node.
// ---------------------------------------------------------------------------
__global__ void mega_kernel(const int*   __restrict__ edge_index,
                            const float* __restrict__ x,
                            const float* __restrict__ node_W,
                            float* __restrict__ out,
                            int N, int E, int SCAT_B, int GEMM_B) {
    __shared__ union {
        float4 sBf[8][4][32];                                    // 16 KB
        struct { float sWT[DD * DD]; float sx[8][DD]; } n;
    } sm;
    int bx = blockIdx.x;
    int tx = threadIdx.x;

    if (bx < SCAT_B) {
        // ---- scatter edges into src-sorted order (2 per thread) ----
        int e0 = bx * 512 + tx;
        int e1 = e0 + 256;
        int s0 = -1, s1 = -1, d0 = 0, d1 = 0;
        if (e0 < E) { s0 = edge_index[e0]; d0 = edge_index[E + e0]; }
        if (e1 < E) { s1 = edge_index[e1]; d1 = edge_index[E + e1]; }
        int p0 = (s0 >= 0) ? atomicAdd(&g_cursor[s0], 1) : 0;
        int p1 = (s1 >= 0) ? atomicAdd(&g_cursor[s1], 1) : 0;
        if (s0 >= 0) { g_perm[p0] = e0; g_ssorted[p0] = s0; g_dsorted[p0] = d0; }
        if (s1 >= 0) { g_perm[p1] = e1; g_ssorted[p1] = s1; g_dsorted[p1] = d1; }
    } else if (bx < SCAT_B + GEMM_B) {
        // ---- Y = x @ W2 via tf32 MMA, 3-pass hi/lo; fp16 store ----
        int gb = bx - SCAT_B;
        int mb = gb >> 4;
        int cb = gb & 15;
        int c0 = cb * 64;

        for (int i = tx; i < 1024; i += 256) {
            float2 h = ((const float2*)g_Bfh)[cb * 1024 + i];
            float2 l = ((const float2*)g_Bfl)[cb * 1024 + i];
            int lane_ = i & 31, ks_ = (i >> 5) & 3, nt_ = i >> 7;
            sm.sBf[nt_][ks_][lane_] = make_float4(h.x, h.y, l.x, l.y);
        }
        __syncthreads();

        int w = tx >> 5, lane = tx & 31;
        int gid = lane >> 2, tig = lane & 3;
        int Nc = N - 1;

        for (int mp = 0; mp < 4; mp++) {
            int rbase = mb * 1024 + w * 128 + mp * 32;
            float C[2][8][4];
            #pragma unroll
            for (int m2 = 0; m2 < 2; m2++)
                #pragma unroll
                for (int nt = 0; nt < 8; nt++)
                    #pragma unroll
                    for (int r = 0; r < 4; r++) C[m2][nt][r] = 0.f;

            #pragma unroll
            for (int ks = 0; ks < 4; ks++) {
                unsigned ah[2][4], al[2][4];
                #pragma unroll
                for (int m2 = 0; m2 < 2; m2++) {
                    int rA  = rbase + m2 * 16;
                    int ra0 = min(rA + gid, Nc);
                    int ra1 = min(rA + gid + 8, Nc);
                    float v0 = x[ra0 * 32 + ks * 8 + tig];
                    float v1 = x[ra1 * 32 + ks * 8 + tig];
                    float v2 = x[ra0 * 32 + ks * 8 + tig + 4];
                    float v3 = x[ra1 * 32 + ks * 8 + tig + 4];
                    split_tf32(v0, ah[m2][0], al[m2][0]);
                    split_tf32(v1, ah[m2][1], al[m2][1]);
                    split_tf32(v2, ah[m2][2], al[m2][2]);
                    split_tf32(v3, ah[m2][3], al[m2][3]);
                }
                #pragma unroll
                for (int nt = 0; nt < 8; nt++) {
                    float4 b = sm.sBf[nt][ks][lane];
                    unsigned bh0 = __float_as_uint(b.x), bh1 = __float_as_uint(b.y);
                    unsigned bl0 = __float_as_uint(b.z), bl1 = __float_as_uint(b.w);
                    #pragma unroll
                    for (int m2 = 0; m2 < 2; m2++) {
                        mma_tf32(C[m2][nt], ah[m2], bh0, bh1);
                        mma_tf32(C[m2][nt], al[m2], bh0, bh1);
                        mma_tf32(C[m2][nt], ah[m2], bl0, bl1);
                    }
                }
            }
            #pragma unroll
            for (int m2 = 0; m2 < 2; m2++) {
                int rA  = rbase + m2 * 16;
                int r0s = rA + gid, r1s = r0s + 8;
                #pragma unroll
                for (int nt = 0; nt < 8; nt++) {
                    int c = c0 + nt * 8 + 2 * tig;
                    if (r0s < N)
                        *(__half2*)&g_Y[(size_t)r0s * KH + c] =
                            __floats2half2_rn(C[m2][nt][0], C[m2][nt][1]);
                    if (r1s < N)
                        *(__half2*)&g_Y[(size_t)r1s * KH + c] =
                            __floats2half2_rn(C[m2][nt][2], C[m2][nt][3]);
                }
            }
        }
    } else {
        // ---- out[i,h] = sum_d x[i,d] * node_W[h,d]  (32 nodes/block) ----
        int nb = bx - SCAT_B - GEMM_B;
        for (int i = tx; i < DD * DD; i += 256) {
            int h = i & 31, d = i >> 5;
            sm.n.sWT[d * 32 + h] = node_W[h * 32 + d];
        }
        __syncthreads();
        int r = tx >> 5, h = tx & 31;
        for (int it = 0; it < 4; it++) {
            int node = nb * 32 + it * 8 + r;
            if (node < N) sm.n.sx[r][h] = x[node * DD + h];
            __syncthreads();
            if (node < N) {
                float acc = 0.f;
                #pragma unroll
                for (int d = 0; d < DD; d++)
                    acc += sm.n.sx[r][d] * sm.n.sWT[d * 32 + h];
                out[node * DD + h] = acc;
            }
            __syncthreads();
        }
    }
}

// ---------------------------------------------------------------------------
// Launch 4: edge messages. Warp = 32 consecutive src-sorted edges (4 warps/blk).
// edge_attr staged in SMEM (pitch 36). Same-src runs via ballot; fp16 Y row
// converted once per run into 32 fp32 regs.
// ---------------------------------------------------------------------------
__global__ void edge_kernel32(const float* __restrict__ edge_attr,
                              float* __restrict__ out, int E) {
    __shared__ float eas[4][32 * 36];   // 18 KB
    int w    = threadIdx.x >> 5;
    int lane = threadIdx.x & 31;
    int gw = blockIdx.x * 4 + w;
    int e0 = gw * 32;
    if (e0 >= E) return;                 // warp-uniform

    int p32 = g_perm[e0 + lane];         // padded region valid for e>=E
    int s32 = g_ssorted[e0 + lane];
    int d32 = g_dsorted[e0 + lane];

    // stage edge_attr rows (zero for padded edges)
    float* easw = &eas[w][0];
    #pragma unroll
    for (int i = 0; i < 32; i++) {
        int pi = __shfl_sync(0xffffffffu, p32, i);
        float v = 0.f;
        if (e0 + i < E) v = edge_attr[(size_t)pi * DD + lane];
        easw[i * 36 + lane] = v;
    }
    __syncwarp();

    // same-src run starts among the 32 edges
    int prevs = __shfl_up_sync(0xffffffffu, s32, 1);
    bool isStart = (lane == 0) || (s32 != prevs);
    unsigned startm = __ballot_sync(0xffffffffu, isStart);

    int g8 = lane & 24;      // k-group base
    int h4 = lane & 7;       // h-quad index
    while (startm) {
        int i = __ffs(startm) - 1;
        startm &= startm - 1;
        int nxt = startm ? (__ffs(startm) - 1) : 32;
        int s = __shfl_sync(0xffffffffu, s32, i);
        const __half* Yrow = g_Y + (size_t)s * KH;
        float4 y[8];
        #pragma unroll
        for (int j = 0; j < 8; j++) {
            uint2 v = *(const uint2*)(Yrow + (g8 + j) * 32 + h4 * 4);
            float2 f01 = __half22float2(*(__half2*)&v.x);
            float2 f23 = __half22float2(*(__half2*)&v.y);
            y[j] = make_float4(f01.x, f01.y, f23.x, f23.y);
        }

        for (int e = i; e < nxt; e++) {
            const float4* ep = (const float4*)(easw + e * 36 + g8);
            float4 f0 = ep[0];
            float4 f1 = ep[1];
            float4 acc;
            acc.x = f0.x * y[0].x; acc.y = f0.x * y[0].y;
            acc.z = f0.x * y[0].z; acc.w = f0.x * y[0].w;
            acc.x += f0.y * y[1].x; acc.y += f0.y * y[1].y;
            acc.z += f0.y * y[1].z; acc.w += f0.y * y[1].w;
            acc.x += f0.z * y[2].x; acc.y += f0.z * y[2].y;
            acc.z += f0.z * y[2].z; acc.w += f0.z * y[2].w;
            acc.x += f0.w * y[3].x; acc.y += f0.w * y[3].y;
            acc.z += f0.w * y[3].z; acc.w += f0.w * y[3].w;
            acc.x += f1.x * y[4].x; acc.y += f1.x * y[4].y;
            acc.z += f1.x * y[4].z; acc.w += f1.x * y[4].w;
            acc.x += f1.y * y[5].x; acc.y += f1.y * y[5].y;
            acc.z += f1.y * y[5].z; acc.w += f1.y * y[5].w;
            acc.x += f1.z * y[6].x; acc.y += f1.z * y[6].y;
            acc.z += f1.z * y[6].z; acc.w += f1.z * y[6].w;
            acc.x += f1.w * y[7].x; acc.y += f1.w * y[7].y;
            acc.z += f1.w * y[7].z; acc.w += f1.w * y[7].w;
            // combine k-group partners (0<->8, 16<->24)
            acc.x += __shfl_xor_sync(0xffffffffu, acc.x, 8);
            acc.y += __shfl_xor_sync(0xffffffffu, acc.y, 8);
            acc.z += __shfl_xor_sync(0xffffffffu, acc.z, 8);
            acc.w += __shfl_xor_sync(0xffffffffu, acc.w, 8);
            int dst = __shfl_sync(0xffffffffu, d32, e);
            if (!(lane & 8))
                red_add_v4(&out[(size_t)dst * DD + h4 * 4], acc);
        }
    }
}

// ---------------------------------------------------------------------------
// Launch.  inputs: 0:x[N*32] 1:edge_attr[E*32] 2:edge_W[1024*32] 3:node_W[32*32]
//          4:edge_index[2*E] i32.  out: [N*32] f32
// ---------------------------------------------------------------------------
extern "C" void kernel_launch(void* const* d_in, const int* in_sizes, int n_in,
                              void* d_out, int out_size) {
    const float* x         = (const float*)d_in[0];
    const float* edge_attr = (const float*)d_in[1];
    const float* edge_W    = (const float*)d_in[2];
    const float* node_W    = (const float*)d_in[3];
    const int*   edge_idx  = (const int*)  d_in[4];
    float* out = (float*)d_out;

    int N = in_sizes[0] / DD;
    int E = in_sizes[4] / 2;
    if (N > N_MAX) N = N_MAX;
    if (E > E_MAX) E = E_MAX;

    // 1. B-fragments + pad + histogram
    int BF_B   = 32768 / 256;                   // 128
    int HIST_B = ((E + 3) / 4 + 255) / 256;
    setup_kernel<<<BF_B + HIST_B, 256>>>(edge_W, edge_idx, E, BF_B);

    // 2. scan -> cursors (+ hist re-zero for graph replay)
    scan_kernel<<<1, 1024>>>(N);

    // 3. scatter | tf32 Y-gemm | node_init
    int SCAT_B = (E + 511) / 512;
    int MB     = (N + 1023) / 1024;
    int GEMM_B = MB * 16;
    int NODE_B = (N + 31) / 32;
    mega_kernel<<<SCAT_B + GEMM_B + NODE_B, 256>>>(edge_idx, x, node_W, out,
                                                   N, E, SCAT_B, GEMM_B);

    // 4. edge messages + vector-red scatter
    int nwarps = (E + 31) / 32;
    edge_kernel32<<<(nwarps + 3) / 4, 128>>>(edge_attr, out, E);
}

// round 9
// speedup vs baseline: 1.5300x; 1.1579x over previous
#include <cuda_runtime.h>
#include <cuda_fp16.h>
#include <cstdint>

// N=25000 nodes, E=400000 edges, D=32.
// out[i,h] = sum_{e: dst_e=i} msgs[e,h] + sum_d x[i,d]*node_W[h,d]
// msgs[e,h] = sum_k edge_attr[e,k] * Y[src_e, k*32+h]
// Y[j, c]   = sum_d x[j,d] * W2[d,c],  W2[d, k*32+h] = edge_W[(d*32+h)*32 + k]

#define DD 32
#define N_MAX 25000
#define E_MAX 400000
#define KH 1024   // D*D

__device__ __half g_Y[(size_t)N_MAX * KH];    // 51.2 MB (fp16)
__device__ float g_Bfh[32768];                // tf32-hi B fragments
__device__ int   g_hist[N_MAX];               // zero at entry; re-zeroed by scan
__device__ int   g_cursor[N_MAX];
__device__ int4  g_meta[E_MAX + 32];          // {perm, src, dst, 0}

__device__ __forceinline__ void red_add_v4(float* addr, float4 v) {
    asm volatile("red.global.add.v4.f32 [%0], {%1,%2,%3,%4};"
                 :: "l"(addr), "f"(v.x), "f"(v.y), "f"(v.z), "f"(v.w)
                 : "memory");
}

__device__ __forceinline__ void mma_tf32(float* c, const unsigned* a,
                                         unsigned b0, unsigned b1) {
    asm volatile(
        "mma.sync.aligned.m16n8k8.row.col.f32.tf32.tf32.f32 "
        "{%0,%1,%2,%3}, {%4,%5,%6,%7}, {%8,%9}, {%0,%1,%2,%3};"
        : "+f"(c[0]), "+f"(c[1]), "+f"(c[2]), "+f"(c[3])
        : "r"(a[0]), "r"(a[1]), "r"(a[2]), "r"(a[3]), "r"(b0), "r"(b1));
}

__device__ __forceinline__ void split_tf32(float v, unsigned& hi, unsigned& lo) {
    unsigned u = __float_as_uint(v) & 0xFFFFE000u;
    hi = u;
    lo = __float_as_uint(v - __uint_as_float(u));
}

// ---------------------------------------------------------------------------
// Launch 1: [0,BF_B): tf32-hi B-fragments + meta pad fill | [BF_B,..): src hist.
// ---------------------------------------------------------------------------
__global__ void setup_kernel(const float* __restrict__ edge_W,
                             const int*   __restrict__ edge_index,
                             int E, int BF_B) {
    if (blockIdx.x < BF_B) {
        int idx = blockIdx.x * 256 + threadIdx.x;
        if (idx < 32768) {
            int reg  = idx & 1;
            int lane = (idx >> 1) & 31;
            int ks   = (idx >> 6) & 3;
            int nt   = idx >> 8;
            int d = ks * 8 + reg * 4 + (lane & 3);
            int c = nt * 8 + (lane >> 2);
            float w = edge_W[(d * 32 + (c & 31)) * 32 + (c >> 5)];
            g_Bfh[idx] = __uint_as_float(__float_as_uint(w) & 0xFFFFE000u);
        }
        if (blockIdx.x == 0 && threadIdx.x < 32)
            g_meta[E + threadIdx.x] = make_int4(0, 0, 0, 0);  // pad region
    } else {
        int base = ((blockIdx.x - BF_B) * 256 + threadIdx.x) * 4;
        #pragma unroll
        for (int j = 0; j < 4; j++) {
            int e = base + j;
            if (e < E) atomicAdd(&g_hist[edge_index[e]], 1);
        }
    }
}

// ---------------------------------------------------------------------------
// Launch 2: single-block exclusive scan -> g_cursor; re-zeroes g_hist.
// ---------------------------------------------------------------------------
__global__ void scan_kernel(int N) {
    __shared__ int wsum[32];
    int t = threadIdx.x;                 // 1024 threads
    int C = (N + 1023) / 1024;
    int base = t * C;

    int total = 0;
    for (int j = 0; j < C; j++) {
        int i = base + j;
        if (i < N) total += g_hist[i];
    }
    int lane = t & 31, wid = t >> 5;
    int incl = total;
    #pragma unroll
    for (int off = 1; off < 32; off <<= 1) {
        int n = __shfl_up_sync(0xffffffffu, incl, off);
        if (lane >= off) incl += n;
    }
    if (lane == 31) wsum[wid] = incl;
    __syncthreads();
    if (wid == 0) {
        int s = wsum[lane];
        #pragma unroll
        for (int off = 1; off < 32; off <<= 1) {
            int n = __shfl_up_sync(0xffffffffu, s, off);
            if (lane >= off) s += n;
        }
        wsum[lane] = s;
    }
    __syncthreads();
    int run = ((wid == 0) ? 0 : wsum[wid - 1]) + incl - total;
    for (int j = 0; j < C; j++) {
        int i = base + j;
        if (i < N) {
            g_cursor[i] = run;
            run += g_hist[i];
            g_hist[i] = 0;            // ready for next graph replay
        }
    }
}

// ---------------------------------------------------------------------------
// Launch 3: mega-kernel. [0,SCAT_B) scatter | [..,+GEMM_B) tf32 Y-gemm | node.
// ---------------------------------------------------------------------------
__global__ void mega_kernel(const int*   __restrict__ edge_index,
                            const float* __restrict__ x,
                            const float* __restrict__ node_W,
                            float* __restrict__ out,
                            int N, int E, int SCAT_B, int GEMM_B) {
    __shared__ union {
        float2 sBf[8][4][32];                                    // 8 KB
        struct { float sWT[DD * DD]; float sx[8][DD]; } n;
    } sm;
    int bx = blockIdx.x;
    int tx = threadIdx.x;

    if (bx < SCAT_B) {
        // ---- scatter edges into src-sorted order (2 per thread) ----
        int e0 = bx * 512 + tx;
        int e1 = e0 + 256;
        int s0 = -1, s1 = -1, d0 = 0, d1 = 0;
        if (e0 < E) { s0 = edge_index[e0]; d0 = edge_index[E + e0]; }
        if (e1 < E) { s1 = edge_index[e1]; d1 = edge_index[E + e1]; }
        int p0 = (s0 >= 0) ? atomicAdd(&g_cursor[s0], 1) : 0;
        int p1 = (s1 >= 0) ? atomicAdd(&g_cursor[s1], 1) : 0;
        if (s0 >= 0) g_meta[p0] = make_int4(e0, s0, d0, 0);
        if (s1 >= 0) g_meta[p1] = make_int4(e1, s1, d1, 0);
    } else if (bx < SCAT_B + GEMM_B) {
        // ---- Y = x @ W2 via tf32 MMA, 2-pass (x hi+lo, W hi); fp16 store ----
        int gb = bx - SCAT_B;
        int mb = gb >> 4;
        int cb = gb & 15;
        int c0 = cb * 64;

        for (int i = tx; i < 1024; i += 256) {
            float2 h = ((const float2*)g_Bfh)[cb * 1024 + i];
            int lane_ = i & 31, ks_ = (i >> 5) & 3, nt_ = i >> 7;
            sm.sBf[nt_][ks_][lane_] = h;
        }
        __syncthreads();

        int w = tx >> 5, lane = tx & 31;
        int gid = lane >> 2, tig = lane & 3;
        int Nc = N - 1;

        for (int mp = 0; mp < 4; mp++) {
            int rbase = mb * 1024 + w * 128 + mp * 32;
            float C[2][8][4];
            #pragma unroll
            for (int m2 = 0; m2 < 2; m2++)
                #pragma unroll
                for (int nt = 0; nt < 8; nt++)
                    #pragma unroll
                    for (int r = 0; r < 4; r++) C[m2][nt][r] = 0.f;

            #pragma unroll
            for (int ks = 0; ks < 4; ks++) {
                unsigned ah[2][4], al[2][4];
                #pragma unroll
                for (int m2 = 0; m2 < 2; m2++) {
                    int rA  = rbase + m2 * 16;
                    int ra0 = min(rA + gid, Nc);
                    int ra1 = min(rA + gid + 8, Nc);
                    float v0 = x[ra0 * 32 + ks * 8 + tig];
                    float v1 = x[ra1 * 32 + ks * 8 + tig];
                    float v2 = x[ra0 * 32 + ks * 8 + tig + 4];
                    float v3 = x[ra1 * 32 + ks * 8 + tig + 4];
                    split_tf32(v0, ah[m2][0], al[m2][0]);
                    split_tf32(v1, ah[m2][1], al[m2][1]);
                    split_tf32(v2, ah[m2][2], al[m2][2]);
                    split_tf32(v3, ah[m2][3], al[m2][3]);
                }
                #pragma unroll
                for (int nt = 0; nt < 8; nt++) {
                    float2 b = sm.sBf[nt][ks][lane];
                    unsigned bh0 = __float_as_uint(b.x), bh1 = __float_as_uint(b.y);
                    #pragma unroll
                    for (int m2 = 0; m2 < 2; m2++) {
                        mma_tf32(C[m2][nt], ah[m2], bh0, bh1);
                        mma_tf32(C[m2][nt], al[m2], bh0, bh1);
                    }
                }
            }
            #pragma unroll
            for (int m2 = 0; m2 < 2; m2++) {
                int rA  = rbase + m2 * 16;
                int r0s = rA + gid, r1s = r0s + 8;
                #pragma unroll
                for (int nt = 0; nt < 8; nt++) {
                    int c = c0 + nt * 8 + 2 * tig;
                    if (r0s < N)
                        *(__half2*)&g_Y[(size_t)r0s * KH + c] =
                            __floats2half2_rn(C[m2][nt][0], C[m2][nt][1]);
                    if (r1s < N)
                        *(__half2*)&g_Y[(size_t)r1s * KH + c] =
                            __floats2half2_rn(C[m2][nt][2], C[m2][nt][3]);
                }
            }
        }
    } else {
        // ---- out[i,h] = sum_d x[i,d] * node_W[h,d]  (32 nodes/block) ----
        int nb = bx - SCAT_B - GEMM_B;
        for (int i = tx; i < DD * DD; i += 256) {
            int h = i & 31, d = i >> 5;
            sm.n.sWT[d * 32 + h] = node_W[h * 32 + d];
        }
        __syncthreads();
        int r = tx >> 5, h = tx & 31;
        for (int it = 0; it < 4; it++) {
            int node = nb * 32 + it * 8 + r;
            if (node < N) sm.n.sx[r][h] = x[node * DD + h];
            __syncthreads();
            if (node < N) {
                float acc = 0.f;
                #pragma unroll
                for (int d = 0; d < DD; d++)
                    acc += sm.n.sx[r][d] * sm.n.sWT[d * 32 + h];
                out[node * DD + h] = acc;
            }
            __syncthreads();
        }
    }
}

// ---------------------------------------------------------------------------
// Launch 4: edge messages. Warp = 32 consecutive src-sorted edges (4 warps/blk).
// edge_attr staged in SMEM (pitch 36 -> broadcast LDS.128). Same-src runs via
// ballot; fp16 Y row converted once per run into 32 fp32 regs.
// ---------------------------------------------------------------------------
__global__ void edge_kernel32(const float* __restrict__ edge_attr,
                              float* __restrict__ out, int E) {
    __shared__ float eas[4][32 * 36];   // 18 KB
    int w    = threadIdx.x >> 5;
    int lane = threadIdx.x & 31;
    int gw = blockIdx.x * 4 + w;
    int e0 = gw * 32;
    if (e0 >= E) return;                 // warp-uniform

    int4 mt = g_meta[e0 + lane];         // {perm, src, dst, 0}; pad valid e>=E
    int p32 = mt.x, s32 = mt.y, d32 = mt.z;

    // stage edge_attr rows (zero for padded edges)
    float* easw = &eas[w][0];
    #pragma unroll
    for (int i = 0; i < 32; i++) {
        int pi = __shfl_sync(0xffffffffu, p32, i);
        float v = 0.f;
        if (e0 + i < E) v = edge_attr[(size_t)pi * DD + lane];
        easw[i * 36 + lane] = v;
    }
    __syncwarp();

    // same-src run starts among the 32 edges
    int prevs = __shfl_up_sync(0xffffffffu, s32, 1);
    bool isStart = (lane == 0) || (s32 != prevs);
    unsigned startm = __ballot_sync(0xffffffffu, isStart);

    int g8 = lane & 24;      // k-group base
    int h4 = lane & 7;       // h-quad index
    while (startm) {
        int i = __ffs(startm) - 1;
        startm &= startm - 1;
        int nxt = startm ? (__ffs(startm) - 1) : 32;
        int s = __shfl_sync(0xffffffffu, s32, i);
        const __half* Yrow = g_Y + (size_t)s * KH;
        float4 y[8];
        #pragma unroll
        for (int j = 0; j < 8; j++) {
            uint2 v = *(const uint2*)(Yrow + (g8 + j) * 32 + h4 * 4);
            float2 f01 = __half22float2(*(__half2*)&v.x);
            float2 f23 = __half22float2(*(__half2*)&v.y);
            y[j] = make_float4(f01.x, f01.y, f23.x, f23.y);
        }

        for (int e = i; e < nxt; e++) {
            const float4* ep = (const float4*)(easw + e * 36 + g8);
            float4 f0 = ep[0];
            float4 f1 = ep[1];
            float4 acc;
            acc.x = f0.x * y[0].x; acc.y = f0.x * y[0].y;
            acc.z = f0.x * y[0].z; acc.w = f0.x * y[0].w;
            acc.x += f0.y * y[1].x; acc.y += f0.y * y[1].y;
            acc.z += f0.y * y[1].z; acc.w += f0.y * y[1].w;
            acc.x += f0.z * y[2].x; acc.y += f0.z * y[2].y;
            acc.z += f0.z * y[2].z; acc.w += f0.z * y[2].w;
            acc.x += f0.w * y[3].x; acc.y += f0.w * y[3].y;
            acc.z += f0.w * y[3].z; acc.w += f0.w * y[3].w;
            acc.x += f1.x * y[4].x; acc.y += f1.x * y[4].y;
            acc.z += f1.x * y[4].z; acc.w += f1.x * y[4].w;
            acc.x += f1.y * y[5].x; acc.y += f1.y * y[5].y;
            acc.z += f1.y * y[5].z; acc.w += f1.y * y[5].w;
            acc.x += f1.z * y[6].x; acc.y += f1.z * y[6].y;
            acc.z += f1.z * y[6].z; acc.w += f1.z * y[6].w;
            acc.x += f1.w * y[7].x; acc.y += f1.w * y[7].y;
            acc.z += f1.w * y[7].z; acc.w += f1.w * y[7].w;
            // combine k-group partners (0<->8, 16<->24)
            acc.x += __shfl_xor_sync(0xffffffffu, acc.x, 8);
            acc.y += __shfl_xor_sync(0xffffffffu, acc.y, 8);
            acc.z += __shfl_xor_sync(0xffffffffu, acc.z, 8);
            acc.w += __shfl_xor_sync(0xffffffffu, acc.w, 8);
            int dst = __shfl_sync(0xffffffffu, d32, e);
            if (!(lane & 8))
                red_add_v4(&out[(size_t)dst * DD + h4 * 4], acc);
        }
    }
}

// ---------------------------------------------------------------------------
// Launch.  inputs: 0:x[N*32] 1:edge_attr[E*32] 2:edge_W[1024*32] 3:node_W[32*32]
//          4:edge_index[2*E] i32.  out: [N*32] f32
// ---------------------------------------------------------------------------
extern "C" void kernel_launch(void* const* d_in, const int* in_sizes, int n_in,
                              void* d_out, int out_size) {
    const float* x         = (const float*)d_in[0];
    const float* edge_attr = (const float*)d_in[1];
    const float* edge_W    = (const float*)d_in[2];
    const float* node_W    = (const float*)d_in[3];
    const int*   edge_idx  = (const int*)  d_in[4];
    float* out = (float*)d_out;

    int N = in_sizes[0] / DD;
    int E = in_sizes[4] / 2;
    if (N > N_MAX) N = N_MAX;
    if (E > E_MAX) E = E_MAX;

    // 1. B-fragments + pad + histogram
    int BF_B   = 32768 / 256;                   // 128
    int HIST_B = ((E + 3) / 4 + 255) / 256;
    setup_kernel<<<BF_B + HIST_B, 256>>>(edge_W, edge_idx, E, BF_B);

    // 2. scan -> cursors (+ hist re-zero for graph replay)
    scan_kernel<<<1, 1024>>>(N);

    // 3. scatter | tf32 Y-gemm | node_init
    int SCAT_B = (E + 511) / 512;
    int MB     = (N + 1023) / 1024;
    int GEMM_B = MB * 16;
    int NODE_B = (N + 31) / 32;
    mega_kernel<<<SCAT_B + GEMM_B + NODE_B, 256>>>(edge_idx, x, node_W, out,
                                                   N, E, SCAT_B, GEMM_B);

    // 4. edge messages + vector-red scatter
    int nwarps = (E + 31) / 32;
    edge_kernel32<<<(nwarps + 3) / 4, 128>>>(edge_attr, out, E);
}